// round 1
// baseline (speedup 1.0000x reference)
#include <cuda_runtime.h>
#include <math.h>

// Problem constants
#define BB 8
#define HH 256
#define WW 256
#define CC 64
#define NKY 8
#define NKX 16

// ---------------- scratch (static device memory; no allocations) ------------
__device__ float g_h[BB*HH*CC*WW];        // h field, layout [b][u][c][v]  (128MB)
__device__ float g_Y[BB*NKY*HH*CC*2];     // stage-1 DFT  [b][ky][u][c][re,im]
__device__ float g_F[BB*NKY*NKX*CC*2];    // modes        [b][ky][s][c][re,im]
__device__ float g_OF[BB*NKY*NKX*CC*2];   // mixed modes  (same layout)
__device__ float g_G[BB*NKY*HH*CC*2];     // inverse stage [b][ky][u][o][re,im]
__device__ float g_Wl2[256*64];           // lift_w2 transposed [k][o]
__device__ float g_Wp1[64*128];           // proj_w1 transposed [k][o]

__device__ __forceinline__ float gelu_f(float x){
    return 0.5f*x*(1.0f + erff(x*0.70710678118654752f));
}

// ---------------- one-time (per launch) weight transposes --------------------
__global__ void k_reorder(const float* __restrict__ lw2, const float* __restrict__ pw1){
    int e = blockIdx.x*256 + threadIdx.x;
    if (e < 256*64){ int k = e>>6, o = e&63;  g_Wl2[e] = lw2[o*256+k]; }
    if (e < 64*128){ int k = e>>7, o = e&127; g_Wp1[e] = pw1[o*64+k]; }
}

// ---------------- lifting: x(3) -> 256 -> gelu -> 64 ------------------------
// grid: B*H*2 (half-row tiles of 128 px), 256 threads
__global__ __launch_bounds__(256) void k_lift(const float* __restrict__ x,
                       const float* __restrict__ w1, const float* __restrict__ b1,
                       const float* __restrict__ b2){
    extern __shared__ float sm[];
    float* t1  = sm;               // 256*129
    float* w2s = t1 + 256*129;     // 16384  [k][o]
    float* w1s = w2s + 16384;      // 768
    float* b1s = w1s + 768;        // 256
    float* b2s = b1s + 256;        // 64
    float* xs  = b2s + 64;         // 3*128
    int tid = threadIdx.x;
    int blk = blockIdx.x;
    int q = blk & 1, u = (blk>>1) & 255, b = blk >> 9;

    for (int i = tid; i < 16384; i += 256) w2s[i] = g_Wl2[i];
    for (int i = tid; i < 768;   i += 256) w1s[i] = w1[i];
    if (tid < 256) b1s[tid] = b1[tid];
    if (tid < 64)  b2s[tid] = b2[tid];
    for (int i = tid; i < 3*128; i += 256){
        int c = i>>7, v = i&127;
        xs[i] = x[((b*3+c)*256+u)*256 + q*128 + v];
    }
    __syncthreads();
    { // phase 1: t1[c][v] = gelu(w1 x + b1), one lift-channel per thread
        int c = tid;
        float a0 = w1s[c*3+0], a1 = w1s[c*3+1], a2 = w1s[c*3+2], bb = b1s[c];
        for (int v = 0; v < 128; v++){
            float s = fmaf(a0, xs[v], fmaf(a1, xs[128+v], fmaf(a2, xs[256+v], bb)));
            t1[c*129+v] = gelu_f(s);
        }
    }
    __syncthreads();
    { // phase 2: h[o][v] = w2 t1 + b2
        int og = tid >> 7;     // 0..1
        int vv = tid & 127;
        int o0 = og*32;
        float acc[32];
        #pragma unroll
        for (int j = 0; j < 32; j++) acc[j] = b2s[o0+j];
        for (int k = 0; k < 256; k++){
            float tv = t1[k*129+vv];
            const float4* wp = (const float4*)&w2s[k*64+o0];
            #pragma unroll
            for (int j4 = 0; j4 < 8; j4++){
                float4 w = wp[j4];
                acc[j4*4+0] = fmaf(tv, w.x, acc[j4*4+0]);
                acc[j4*4+1] = fmaf(tv, w.y, acc[j4*4+1]);
                acc[j4*4+2] = fmaf(tv, w.z, acc[j4*4+2]);
                acc[j4*4+3] = fmaf(tv, w.w, acc[j4*4+3]);
            }
        }
        float* outrow = g_h + (size_t)((b*256+u)*64)*256 + q*128;
        #pragma unroll
        for (int j = 0; j < 32; j++) outrow[(o0+j)*256 + vv] = acc[j];
    }
}

// ---------------- DFT stage 1 (over v, rfft axis), forward norm --------------
// grid: B*H, 256 threads. Y[b][ky][u][c] = (1/65536) sum_v h * e^{-2pi i ky v/256}
__global__ __launch_bounds__(256) void k_dft1(){
    extern __shared__ float sm[];
    float* hs = sm;            // 64*257
    float* tw = hs + 64*257;   // 8*256*2
    int tid = threadIdx.x;
    int u = blockIdx.x & 255, b = blockIdx.x >> 8;
    const float* row = g_h + (size_t)(b*256+u)*64*256;
    for (int i = tid; i < 64*256; i += 256){
        hs[(i>>8)*257 + (i&255)] = row[i];
    }
    for (int i = tid; i < 8*256; i += 256){
        int ky = i>>8, v = i&255;
        float ss, sc;
        sincospif(-(float)(ky*v)*(1.0f/128.0f), &ss, &sc);
        tw[i*2] = sc; tw[i*2+1] = ss;    // e^{-i th} = (cos, -sin) = (sc, ss)
    }
    __syncthreads();
    int ky = tid >> 5, cl = tid & 31;
    const float scale = 1.0f/65536.0f;
    const float2* twp = (const float2*)&tw[ky*512];
    #pragma unroll
    for (int cc = 0; cc < 2; cc++){
        int c = cl + cc*32;
        float sr = 0.f, si = 0.f;
        const float* hrow = &hs[c*257];
        for (int v = 0; v < 256; v++){
            float xv = hrow[v];
            float2 t = twp[v];
            sr = fmaf(xv, t.x, sr);
            si = fmaf(xv, t.y, si);
        }
        float* o = g_Y + (size_t)(((b*8+ky)*256+u)*64 + c)*2;
        o[0] = sr*scale; o[1] = si*scale;
    }
}

// ---------------- DFT stage 2 (over u): 16 kx slots {0..7, -8..-1} ----------
// grid: B*KY = 64, 256 threads (16 kx-slots x 16 channel-groups of 4)
__global__ __launch_bounds__(256) void k_dft2(){
    __shared__ float tw[16*256*2];
    int tid = threadIdx.x;
    int b = blockIdx.x >> 3, ky = blockIdx.x & 7;
    for (int i = tid; i < 16*256; i += 256){
        int s = i>>8, u = i&255;
        int kxe = (s < 8) ? s : s - 16;
        float ss, sc;
        sincospif(-(float)(kxe*u)*(1.0f/128.0f), &ss, &sc);
        tw[i*2] = sc; tw[i*2+1] = ss;
    }
    __syncthreads();
    int s = tid >> 4, cg = tid & 15, c0 = cg*4;
    float ar[4] = {0,0,0,0}, ai[4] = {0,0,0,0};
    const float* Ybase = g_Y + (size_t)((b*8+ky)*256)*128;
    const float2* twp = (const float2*)&tw[s*512];
    for (int u = 0; u < 256; u++){
        const float4* yp = (const float4*)(Ybase + u*128 + c0*2);
        float4 y0 = yp[0], y1 = yp[1];
        float2 t = twp[u];
        ar[0] = fmaf(y0.x, t.x, fmaf(-y0.y, t.y, ar[0]));
        ai[0] = fmaf(y0.x, t.y, fmaf( y0.y, t.x, ai[0]));
        ar[1] = fmaf(y0.z, t.x, fmaf(-y0.w, t.y, ar[1]));
        ai[1] = fmaf(y0.z, t.y, fmaf( y0.w, t.x, ai[1]));
        ar[2] = fmaf(y1.x, t.x, fmaf(-y1.y, t.y, ar[2]));
        ai[2] = fmaf(y1.x, t.y, fmaf( y1.y, t.x, ai[2]));
        ar[3] = fmaf(y1.z, t.x, fmaf(-y1.w, t.y, ar[3]));
        ai[3] = fmaf(y1.z, t.y, fmaf( y1.w, t.x, ai[3]));
    }
    float* o = g_F + (size_t)(((b*8+ky)*16+s)*64 + c0)*2;
    #pragma unroll
    for (int j = 0; j < 4; j++){ o[j*2] = ar[j]; o[j*2+1] = ai[j]; }
}

// ---------------- mode mixing: out[o] = sum_i F[i] * W[i][o] (complex) ------
// grid: KX*KY = 128 (one mode each), 256 threads
__global__ __launch_bounds__(256) void k_mix(int l, const float* __restrict__ wr1,
                      const float* __restrict__ wi1, const float* __restrict__ wr2,
                      const float* __restrict__ wi2){
    __shared__ float Fs[8*64*2];
    __shared__ float Wm[64*64*2];
    int tid = threadIdx.x;
    int s = blockIdx.x >> 3, ky = blockIdx.x & 7;
    const float* wr = (s < 8) ? wr1 : wr2;
    const float* wi = (s < 8) ? wi1 : wi2;
    int kxh = s & 7;
    for (int i = tid; i < 8*64*2; i += 256){
        int b = i >> 7, r = i & 127;
        Fs[i] = g_F[(size_t)(((b*8+ky)*16+s)*64)*2 + r];
    }
    for (int i = tid; i < 4096; i += 256){
        int ii = i >> 6, o = i & 63;
        int src = (((l*64+ii)*64+o)*8 + kxh)*8 + ky;
        Wm[i*2]   = wr[src];
        Wm[i*2+1] = wi[src];
    }
    __syncthreads();
    #pragma unroll
    for (int p = 0; p < 2; p++){
        int gid = tid + p*256;
        int b = gid >> 6, o = gid & 63;
        float ar = 0.f, ai = 0.f;
        const float2* fp = (const float2*)&Fs[b*128];
        const float2* wp = (const float2*)Wm;
        for (int i2 = 0; i2 < 64; i2++){
            float2 f = fp[i2];
            float2 w = wp[i2*64 + o];
            ar = fmaf(f.x, w.x, fmaf(-f.y, w.y, ar));
            ai = fmaf(f.x, w.y, fmaf( f.y, w.x, ai));
        }
        float* ot = g_OF + (size_t)(((b*8+ky)*16+s)*64 + o)*2;
        ot[0] = ar; ot[1] = ai;
    }
}

// ---------------- inverse over kx: G[ky][u][o] = sum_s OF * e^{+2pi i kx u/H}
// grid: B*KY*4 = 256, 256 threads (64 u x 4 o-groups of 16)
__global__ __launch_bounds__(256) void k_idft1(){
    __shared__ float OFs[16*64*2];
    int tid = threadIdx.x;
    int blk = blockIdx.x;
    int uq = blk & 3, ky = (blk>>2) & 7, b = blk >> 5;
    for (int i = tid; i < 2048; i += 256)
        OFs[i] = g_OF[(size_t)((b*8+ky)*16*64)*2 + i];
    __syncthreads();
    int u = uq*64 + (tid & 63);
    int og = tid >> 6, o0 = og*16;
    float ar[16], ai[16];
    #pragma unroll
    for (int j = 0; j < 16; j++){ ar[j] = 0.f; ai[j] = 0.f; }
    for (int s = 0; s < 16; s++){
        int kxe = (s < 8) ? s : s - 16;
        float ss, sc;
        sincospif((float)(kxe*u)*(1.0f/128.0f), &ss, &sc);
        const float2* op = (const float2*)&OFs[(s*64+o0)*2];
        #pragma unroll
        for (int j = 0; j < 16; j++){
            float2 f = op[j];
            ar[j] = fmaf(f.x, sc, fmaf(-f.y, ss, ar[j]));
            ai[j] = fmaf(f.x, ss, fmaf( f.y, sc, ai[j]));
        }
    }
    float* o = g_G + (size_t)(((b*8+ky)*256+u)*64 + o0)*2;
    #pragma unroll
    for (int j = 0; j < 16; j++){ o[j*2] = ar[j]; o[j*2+1] = ai[j]; }
}

// ---------------- fused per-row layer kernel --------------------------------
// x_fno = irfft-recombine(G) + spec_b; t = gelu(x_fno + Wskip h);
// m = W2 gelu(W1 t + b1) + b2; h = m + gate*h; gelu if l<3.  In-place on g_h.
// grid: B*H = 2048 rows, 256 threads. Tiling: 4 c-groups x 64 v-groups,
// each thread owns 16 channels x 4 pixels.
__global__ __launch_bounds__(256) void k_fuse(int l,
        const float* __restrict__ wskip_g, const float* __restrict__ gate_g,
        const float* __restrict__ specb_g, const float* __restrict__ w1_g,
        const float* __restrict__ b1_g, const float* __restrict__ w2_g,
        const float* __restrict__ b2_g){
    extern __shared__ float sm[];
    float* hs  = sm;              // 64*260
    float* ts  = hs + 64*260;     // 64*260
    float* ms  = ts + 64*260;     // 32*260
    float* wsk = ms + 32*260;     // 4096 [i][o]
    float* w1  = wsk + 4096;      // 2048 [i][j]
    float* w2  = w1 + 2048;       // 2048 [j][o]
    float* Gr  = w2 + 2048;       // 1024 [ky][o][2]
    float* gw  = Gr + 1024;       // 64
    float* sb  = gw + 64;         // 64
    float* b1  = sb + 64;         // 32
    float* b2  = b1 + 32;         // 64
    int tid = threadIdx.x;
    int u = blockIdx.x & 255, b = blockIdx.x >> 8;
    float* row = g_h + (size_t)(b*256+u)*64*256;

    for (int i = tid; i < 16384; i += 256) hs[(i>>8)*260 + (i&255)] = row[i];
    for (int i = tid; i < 4096; i += 256){ int ii = i>>6, o = i&63; wsk[i] = wskip_g[l*4096 + o*64 + ii]; }
    for (int i = tid; i < 2048; i += 256){ int ii = i>>5, j = i&31; w1[i]  = w1_g[l*2048 + j*64 + ii]; }
    for (int i = tid; i < 2048; i += 256){ int j = i>>6, o = i&63;  w2[i]  = w2_g[l*2048 + o*32 + j]; }
    for (int i = tid; i < 1024; i += 256){ int ky = i>>7, r = i&127; Gr[i] = g_G[(size_t)(((b*8+ky)*256+u)*64)*2 + r]; }
    if (tid < 64) gw[tid] = gate_g[l*64+tid];
    if (tid < 64) sb[tid] = specb_g[l*64+tid];
    if (tid < 32) b1[tid] = b1_g[l*32+tid];
    if (tid < 64) b2[tid] = b2_g[l*64+tid];
    __syncthreads();

    int cg = tid >> 6, vg = tid & 63;
    int o0 = cg*16, v0 = vg*4;

    // ---- phase 1: x_fno + skip_fno, gelu -> ts
    {
        float acc[16][4];
        #pragma unroll
        for (int j = 0; j < 16; j++){
            float s = sb[o0+j];
            #pragma unroll
            for (int p = 0; p < 4; p++) acc[j][p] = s;
        }
        // spectral recombination: sum_ky c_ky * Re(G * e^{+2pi i ky v/256})
        for (int ky = 0; ky < 8; ky++){
            float cw = (ky == 0) ? 1.0f : 2.0f;
            float cs[4], sn[4];
            #pragma unroll
            for (int p = 0; p < 4; p++){
                float ss, sc;
                sincospif((float)(ky*(v0+p))*(1.0f/128.0f), &ss, &sc);
                cs[p] = sc*cw; sn[p] = ss*cw;
            }
            const float2* gp = (const float2*)&Gr[(ky*64+o0)*2];
            #pragma unroll
            for (int j = 0; j < 16; j++){
                float2 g = gp[j];
                #pragma unroll
                for (int p = 0; p < 4; p++)
                    acc[j][p] = fmaf(g.x, cs[p], fmaf(-g.y, sn[p], acc[j][p]));
            }
        }
        // skip GEMM: acc[o][p] += sum_i h[i][p] * Wskip[i][o]
        for (int i = 0; i < 64; i++){
            float4 hv = *(const float4*)&hs[i*260 + v0];
            float hp[4] = {hv.x, hv.y, hv.z, hv.w};
            const float4* wp = (const float4*)&wsk[i*64 + o0];
            #pragma unroll
            for (int j4 = 0; j4 < 4; j4++){
                float4 w = wp[j4];
                float wq[4] = {w.x, w.y, w.z, w.w};
                #pragma unroll
                for (int jj = 0; jj < 4; jj++)
                    #pragma unroll
                    for (int p = 0; p < 4; p++)
                        acc[j4*4+jj][p] = fmaf(hp[p], wq[jj], acc[j4*4+jj][p]);
            }
        }
        #pragma unroll
        for (int j = 0; j < 16; j++){
            float4 tv;
            tv.x = gelu_f(acc[j][0]); tv.y = gelu_f(acc[j][1]);
            tv.z = gelu_f(acc[j][2]); tv.w = gelu_f(acc[j][3]);
            *(float4*)&ts[(o0+j)*260 + v0] = tv;
        }
    }
    __syncthreads();

    // ---- phase 2: m = gelu(W1 t + b1) -> ms (32 channels)
    {
        int j0 = cg*8;
        float a2[8][4];
        #pragma unroll
        for (int j = 0; j < 8; j++){
            float s = b1[j0+j];
            #pragma unroll
            for (int p = 0; p < 4; p++) a2[j][p] = s;
        }
        for (int i = 0; i < 64; i++){
            float4 tv = *(const float4*)&ts[i*260 + v0];
            float tp[4] = {tv.x, tv.y, tv.z, tv.w};
            const float4* wp = (const float4*)&w1[i*32 + j0];
            #pragma unroll
            for (int j4 = 0; j4 < 2; j4++){
                float4 w = wp[j4];
                float wq[4] = {w.x, w.y, w.z, w.w};
                #pragma unroll
                for (int jj = 0; jj < 4; jj++)
                    #pragma unroll
                    for (int p = 0; p < 4; p++)
                        a2[j4*4+jj][p] = fmaf(tp[p], wq[jj], a2[j4*4+jj][p]);
            }
        }
        #pragma unroll
        for (int j = 0; j < 8; j++){
            float4 mv;
            mv.x = gelu_f(a2[j][0]); mv.y = gelu_f(a2[j][1]);
            mv.z = gelu_f(a2[j][2]); mv.w = gelu_f(a2[j][3]);
            *(float4*)&ms[(j0+j)*260 + v0] = mv;
        }
    }
    __syncthreads();

    // ---- phase 3: h = W2 m + b2 + gate*h_old (+ gelu if l<3)
    {
        float a3[16][4];
        #pragma unroll
        for (int j = 0; j < 16; j++){
            float s = b2[o0+j];
            #pragma unroll
            for (int p = 0; p < 4; p++) a3[j][p] = s;
        }
        for (int j2 = 0; j2 < 32; j2++){
            float4 mv = *(const float4*)&ms[j2*260 + v0];
            float mp[4] = {mv.x, mv.y, mv.z, mv.w};
            const float4* wp = (const float4*)&w2[j2*64 + o0];
            #pragma unroll
            for (int j4 = 0; j4 < 4; j4++){
                float4 w = wp[j4];
                float wq[4] = {w.x, w.y, w.z, w.w};
                #pragma unroll
                for (int jj = 0; jj < 4; jj++)
                    #pragma unroll
                    for (int p = 0; p < 4; p++)
                        a3[j4*4+jj][p] = fmaf(mp[p], wq[jj], a3[j4*4+jj][p]);
            }
        }
        bool dog = (l < 3);
        #pragma unroll
        for (int j = 0; j < 16; j++){
            float g = gw[o0+j];
            float4 hv = *(const float4*)&hs[(o0+j)*260 + v0];
            float4 ov;
            ov.x = fmaf(g, hv.x, a3[j][0]);
            ov.y = fmaf(g, hv.y, a3[j][1]);
            ov.z = fmaf(g, hv.z, a3[j][2]);
            ov.w = fmaf(g, hv.w, a3[j][3]);
            if (dog){
                ov.x = gelu_f(ov.x); ov.y = gelu_f(ov.y);
                ov.z = gelu_f(ov.z); ov.w = gelu_f(ov.w);
            }
            *(float4*)&row[(o0+j)*256 + v0] = ov;
        }
    }
}

// ---------------- projection: 64 -> 128 -> gelu -> 3, + input residual ------
// grid: B*H*4 (64-px tiles), 256 threads
__global__ __launch_bounds__(256) void k_proj(const float* __restrict__ x,
                      const float* __restrict__ b1g, const float* __restrict__ w2g,
                      const float* __restrict__ b2g, float* __restrict__ out){
    extern __shared__ float sm[];
    float* hsp = sm;            // 64*65
    float* t2  = hsp + 64*65;   // 128*65
    float* w1s = t2 + 128*65;   // 64*128 [k][o]
    float* b1s = w1s + 8192;    // 128
    int tid = threadIdx.x;
    int blk = blockIdx.x;
    int q = blk & 3, u = (blk>>2) & 255, b = blk >> 10;
    const float* row = g_h + (size_t)(b*256+u)*64*256 + q*64;
    for (int i = tid; i < 64*64; i += 256){ int c = i>>6, v = i&63; hsp[c*65+v] = row[c*256+v]; }
    for (int i = tid; i < 8192;  i += 256) w1s[i] = g_Wp1[i];
    if (tid < 128) b1s[tid] = b1g[tid];
    __syncthreads();
    {
        int og = tid >> 6, vv = tid & 63;
        int o0 = og*32;
        float a[32];
        #pragma unroll
        for (int j = 0; j < 32; j++) a[j] = b1s[o0+j];
        for (int k = 0; k < 64; k++){
            float hv = hsp[k*65+vv];
            const float4* wp = (const float4*)&w1s[k*128+o0];
            #pragma unroll
            for (int j4 = 0; j4 < 8; j4++){
                float4 w = wp[j4];
                a[j4*4+0] = fmaf(hv, w.x, a[j4*4+0]);
                a[j4*4+1] = fmaf(hv, w.y, a[j4*4+1]);
                a[j4*4+2] = fmaf(hv, w.z, a[j4*4+2]);
                a[j4*4+3] = fmaf(hv, w.w, a[j4*4+3]);
            }
        }
        #pragma unroll
        for (int j = 0; j < 32; j++) t2[(o0+j)*65+vv] = gelu_f(a[j]);
    }
    __syncthreads();
    if (tid < 192){
        int c = tid >> 6, vv = tid & 63;
        float a = b2g[c];
        for (int j = 0; j < 128; j++)
            a = fmaf(t2[j*65+vv], w2g[c*128+j], a);
        size_t gi = (size_t)((b*3+c)*256+u)*256 + q*64 + vv;
        out[gi] = a + x[gi];
    }
}

// ---------------- host launch ------------------------------------------------
extern "C" void kernel_launch(void* const* d_in, const int* in_sizes, int n_in,
                              void* d_out, int out_size){
    (void)in_sizes; (void)n_in; (void)out_size;
    const float* x       = (const float*)d_in[0];
    const float* lift_w1 = (const float*)d_in[1];
    const float* lift_b1 = (const float*)d_in[2];
    const float* lift_w2 = (const float*)d_in[3];
    const float* lift_b2 = (const float*)d_in[4];
    const float* swr1    = (const float*)d_in[5];
    const float* swi1    = (const float*)d_in[6];
    const float* swr2    = (const float*)d_in[7];
    const float* swi2    = (const float*)d_in[8];
    const float* spec_b  = (const float*)d_in[9];
    const float* skw     = (const float*)d_in[10];
    const float* gate    = (const float*)d_in[11];
    const float* mw1     = (const float*)d_in[12];
    const float* mb1     = (const float*)d_in[13];
    const float* mw2     = (const float*)d_in[14];
    const float* mb2     = (const float*)d_in[15];
    const float* pw1     = (const float*)d_in[16];
    const float* pb1     = (const float*)d_in[17];
    const float* pw2     = (const float*)d_in[18];
    const float* pb2     = (const float*)d_in[19];
    float* out = (float*)d_out;

    const int SM_LIFT = (256*129 + 16384 + 768 + 256 + 64 + 384) * 4;   // 203520
    const int SM_DFT1 = (64*257 + 8*256*2) * 4;                          // 82176
    const int SM_FUSE = (64*260*2 + 32*260 + 4096 + 2048 + 2048 + 1024 + 64 + 64 + 32 + 64) * 4; // 204160
    const int SM_PROJ = (64*65 + 128*65 + 8192 + 128) * 4;               // 83200

    cudaFuncSetAttribute(k_lift, cudaFuncAttributeMaxDynamicSharedMemorySize, SM_LIFT);
    cudaFuncSetAttribute(k_dft1, cudaFuncAttributeMaxDynamicSharedMemorySize, SM_DFT1);
    cudaFuncSetAttribute(k_fuse, cudaFuncAttributeMaxDynamicSharedMemorySize, SM_FUSE);
    cudaFuncSetAttribute(k_proj, cudaFuncAttributeMaxDynamicSharedMemorySize, SM_PROJ);

    k_reorder<<<64, 256>>>(lift_w2, pw1);
    k_lift<<<BB*HH*2, 256, SM_LIFT>>>(x, lift_w1, lift_b1, lift_b2);
    for (int l = 0; l < 4; l++){
        k_dft1 <<<BB*HH, 256, SM_DFT1>>>();
        k_dft2 <<<BB*NKY, 256>>>();
        k_mix  <<<NKX*NKY, 256>>>(l, swr1, swi1, swr2, swi2);
        k_idft1<<<BB*NKY*4, 256>>>();
        k_fuse <<<BB*HH, 256, SM_FUSE>>>(l, skw, gate, spec_b, mw1, mb1, mw2, mb2);
    }
    k_proj<<<BB*HH*4, 256, SM_PROJ>>>(x, pb1, pw2, pb2, out);
}

// round 2
// speedup vs baseline: 1.1741x; 1.1741x over previous
#include <cuda_runtime.h>
#include <math.h>

// Problem constants
#define BB 8
#define HH 256
#define WW 256
#define CC 64
#define NKY 8
#define NKX 16

// ---------------- scratch (static device memory; no allocations) ------------
__device__ float g_h[BB*HH*CC*WW];        // h field, layout [b][u][c][v]  (128MB)
__device__ float g_Y[BB*NKY*HH*CC*2];     // stage-1 DFT  [b][ky][u][c][re,im]
__device__ float g_F[BB*NKY*NKX*CC*2];    // modes        [b][ky][s][c][re,im]
__device__ float g_OF[BB*NKY*NKX*CC*2];   // mixed modes  (same layout)
__device__ float g_G[BB*NKY*HH*CC*2];     // inverse stage [b][ky][u][o][re,im]
__device__ float g_Wl2[256*64];           // lift_w2 transposed [k][o]
__device__ float g_Wp1[64*128];           // proj_w1 transposed [k][o]

__device__ __forceinline__ float gelu_f(float x){
    return 0.5f*x*(1.0f + erff(x*0.70710678118654752f));
}

// ---------------- one-time (per launch) weight transposes --------------------
__global__ void k_reorder(const float* __restrict__ lw2, const float* __restrict__ pw1){
    int e = blockIdx.x*256 + threadIdx.x;
    if (e < 256*64){ int k = e>>6, o = e&63;  g_Wl2[e] = lw2[o*256+k]; }
    if (e < 64*128){ int k = e>>7, o = e&127; g_Wp1[e] = pw1[o*64+k]; }
}

// ---------------- lifting: x(3) -> 256 -> gelu -> 64 ------------------------
// grid: B*H*2 (half-row tiles of 128 px), 256 threads, 2 blocks/SM.
// Two passes over K-halves of the 256-wide hidden layer to halve smem.
__global__ __launch_bounds__(256,2) void k_lift(const float* __restrict__ x,
                       const float* __restrict__ w1, const float* __restrict__ b1,
                       const float* __restrict__ b2){
    extern __shared__ float sm[];
    float* t1  = sm;               // 128*129 = 16512
    float* w2h = t1 + 16512;       // 8192  [kk][o] (half of lift_w2)
    float* w1s = w2h + 8192;       // 768
    float* b1s = w1s + 768;        // 256
    float* b2s = b1s + 256;        // 64
    float* xs  = b2s + 64;         // 3*128
    int tid = threadIdx.x;
    int blk = blockIdx.x;
    int q = blk & 1, u = (blk>>1) & 255, b = blk >> 9;

    for (int i = tid; i < 768; i += 256) w1s[i] = w1[i];
    if (tid < 256) b1s[tid] = b1[tid];
    if (tid < 64)  b2s[tid] = b2[tid];
    for (int i = tid; i < 3*128; i += 256){
        int c = i>>7, v = i&127;
        xs[i] = x[((b*3+c)*256+u)*256 + q*128 + v];
    }
    __syncthreads();

    int og = tid >> 7, vv = tid & 127, o0 = og*32;
    float acc[32];
    #pragma unroll
    for (int j = 0; j < 32; j++) acc[j] = b2s[o0+j];

    for (int p = 0; p < 2; p++){
        // load this K-half of w2 and compute this half of t1
        for (int i = tid; i < 8192; i += 256) w2h[i] = g_Wl2[p*8192 + i];
        for (int it = tid; it < 16384; it += 256){
            int kk = it >> 7, vx = it & 127;
            int c = p*128 + kk;
            float s = fmaf(w1s[c*3+0], xs[vx],
                      fmaf(w1s[c*3+1], xs[128+vx],
                      fmaf(w1s[c*3+2], xs[256+vx], b1s[c])));
            t1[kk*129+vx] = gelu_f(s);
        }
        __syncthreads();
        for (int kk = 0; kk < 128; kk++){
            float tv = t1[kk*129+vv];
            const float4* wp = (const float4*)&w2h[kk*64+o0];
            #pragma unroll
            for (int j4 = 0; j4 < 8; j4++){
                float4 w = wp[j4];
                acc[j4*4+0] = fmaf(tv, w.x, acc[j4*4+0]);
                acc[j4*4+1] = fmaf(tv, w.y, acc[j4*4+1]);
                acc[j4*4+2] = fmaf(tv, w.z, acc[j4*4+2]);
                acc[j4*4+3] = fmaf(tv, w.w, acc[j4*4+3]);
            }
        }
        __syncthreads();   // protect t1/w2h before next pass overwrites
    }
    float* outrow = g_h + (size_t)((b*256+u)*64)*256 + q*128;
    #pragma unroll
    for (int j = 0; j < 32; j++) outrow[(o0+j)*256 + vv] = acc[j];
}

// ---------------- DFT stage 1 (over v): runs ONCE after lift -----------------
__global__ __launch_bounds__(256) void k_dft1(){
    extern __shared__ float sm[];
    float* hs = sm;            // 64*257
    float* tw = hs + 64*257;   // 8*256*2
    int tid = threadIdx.x;
    int u = blockIdx.x & 255, b = blockIdx.x >> 8;
    const float* row = g_h + (size_t)(b*256+u)*64*256;
    for (int i = tid; i < 64*256; i += 256){
        hs[(i>>8)*257 + (i&255)] = row[i];
    }
    for (int i = tid; i < 8*256; i += 256){
        int ky = i>>8, v = i&255;
        float ss, sc;
        sincospif(-(float)(ky*v)*(1.0f/128.0f), &ss, &sc);
        tw[i*2] = sc; tw[i*2+1] = ss;
    }
    __syncthreads();
    int ky = tid >> 5, cl = tid & 31;
    const float scale = 1.0f/65536.0f;
    const float2* twp = (const float2*)&tw[ky*512];
    #pragma unroll
    for (int cc = 0; cc < 2; cc++){
        int c = cl + cc*32;
        float sr = 0.f, si = 0.f;
        const float* hrow = &hs[c*257];
        for (int v = 0; v < 256; v++){
            float xv = hrow[v];
            float2 t = twp[v];
            sr = fmaf(xv, t.x, sr);
            si = fmaf(xv, t.y, si);
        }
        float* o = g_Y + (size_t)(((b*8+ky)*256+u)*64 + c)*2;
        o[0] = sr*scale; o[1] = si*scale;
    }
}

// ---------------- DFT stage 2 (over u): grid B*KY*KX = 1024 -----------------
__global__ __launch_bounds__(256) void k_dft2(){
    __shared__ float tc[256], tsp[256];
    __shared__ float red[4*64*2];
    int tid = threadIdx.x;
    int blk = blockIdx.x;
    int s = blk & 15, ky = (blk>>4) & 7, b = blk >> 7;
    int kxe = (s < 8) ? s : s - 16;
    {
        float ss, sc;
        sincospif((float)tid*(1.0f/128.0f), &ss, &sc);
        tc[tid] = sc; tsp[tid] = ss;
    }
    __syncthreads();
    int uc = tid >> 6, c = tid & 63;
    float sr = 0.f, si = 0.f;
    const float* Yb = g_Y + (size_t)((b*8+ky)*256)*128;
    int u0 = uc*64;
    for (int uu = 0; uu < 64; uu++){
        int u = u0 + uu;
        int t = (kxe*u) & 255;
        float2 y = *(const float2*)(Yb + u*128 + c*2);
        float cc = tc[t], sv = tsp[t];
        sr = fmaf(y.x, cc, fmaf( y.y, sv, sr));
        si = fmaf(y.y, cc, fmaf(-y.x, sv, si));
    }
    red[(uc*64+c)*2]   = sr;
    red[(uc*64+c)*2+1] = si;
    __syncthreads();
    if (tid < 64){
        float ar = red[tid*2]       + red[(64+tid)*2]
                 + red[(128+tid)*2] + red[(192+tid)*2];
        float ai = red[tid*2+1]       + red[(64+tid)*2+1]
                 + red[(128+tid)*2+1] + red[(192+tid)*2+1];
        float* o = g_F + (size_t)(((b*8+ky)*16+s)*64 + tid)*2;
        o[0] = ar; o[1] = ai;
    }
}

// ---------------- mode mixing: out[o] = sum_i F[i] * W[i][o] (complex) ------
__global__ __launch_bounds__(256) void k_mix(int l, const float* __restrict__ wr1,
                      const float* __restrict__ wi1, const float* __restrict__ wr2,
                      const float* __restrict__ wi2){
    __shared__ float Fs[8*64*2];
    __shared__ float Wm[64*64*2];
    int tid = threadIdx.x;
    int s = blockIdx.x >> 3, ky = blockIdx.x & 7;
    const float* wr = (s < 8) ? wr1 : wr2;
    const float* wi = (s < 8) ? wi1 : wi2;
    int kxh = s & 7;
    for (int i = tid; i < 8*64*2; i += 256){
        int b = i >> 7, r = i & 127;
        Fs[i] = g_F[(size_t)(((b*8+ky)*16+s)*64)*2 + r];
    }
    for (int i = tid; i < 4096; i += 256){
        int ii = i >> 6, o = i & 63;
        int src = (((l*64+ii)*64+o)*8 + kxh)*8 + ky;
        Wm[i*2]   = wr[src];
        Wm[i*2+1] = wi[src];
    }
    __syncthreads();
    #pragma unroll
    for (int p = 0; p < 2; p++){
        int gid = tid + p*256;
        int b = gid >> 6, o = gid & 63;
        float ar = 0.f, ai = 0.f;
        const float2* fp = (const float2*)&Fs[b*128];
        const float2* wp = (const float2*)Wm;
        for (int i2 = 0; i2 < 64; i2++){
            float2 f = fp[i2];
            float2 w = wp[i2*64 + o];
            ar = fmaf(f.x, w.x, fmaf(-f.y, w.y, ar));
            ai = fmaf(f.x, w.y, fmaf( f.y, w.x, ai));
        }
        float* ot = g_OF + (size_t)(((b*8+ky)*16+s)*64 + o)*2;
        ot[0] = ar; ot[1] = ai;
    }
}

// ---------------- inverse over kx ------------------------------------------
__global__ __launch_bounds__(256) void k_idft1(){
    __shared__ float OFs[16*64*2];
    int tid = threadIdx.x;
    int blk = blockIdx.x;
    int uq = blk & 3, ky = (blk>>2) & 7, b = blk >> 5;
    for (int i = tid; i < 2048; i += 256)
        OFs[i] = g_OF[(size_t)((b*8+ky)*16*64)*2 + i];
    __syncthreads();
    int u = uq*64 + (tid & 63);
    int og = tid >> 6, o0 = og*16;
    float ar[16], ai[16];
    #pragma unroll
    for (int j = 0; j < 16; j++){ ar[j] = 0.f; ai[j] = 0.f; }
    for (int s = 0; s < 16; s++){
        int kxe = (s < 8) ? s : s - 16;
        float ss, sc;
        sincospif((float)(kxe*u)*(1.0f/128.0f), &ss, &sc);
        const float2* op = (const float2*)&OFs[(s*64+o0)*2];
        #pragma unroll
        for (int j = 0; j < 16; j++){
            float2 f = op[j];
            ar[j] = fmaf(f.x, sc, fmaf(-f.y, ss, ar[j]));
            ai[j] = fmaf(f.x, ss, fmaf( f.y, sc, ai[j]));
        }
    }
    float* o = g_G + (size_t)(((b*8+ky)*256+u)*64 + o0)*2;
    #pragma unroll
    for (int j = 0; j < 16; j++){ o[j*2] = ar[j]; o[j*2+1] = ai[j]; }
}

// ---------------- fused per-row layer kernel (thread = pixel) ---------------
// All 64 channels register-resident per thread. Also computes next layer's
// stage-1 DFT as an epilogue (do_dft) to kill the separate k_dft1 passes.
__global__ __launch_bounds__(256,2) void k_fuse(int l, int do_dft,
        const float* __restrict__ wskip_g, const float* __restrict__ gate_g,
        const float* __restrict__ specb_g, const float* __restrict__ w1_g,
        const float* __restrict__ b1_g, const float* __restrict__ w2_g,
        const float* __restrict__ b2_g){
    extern __shared__ float sm[];
    float* hs  = sm;              // 64*257 = 16448
    float* wsk = hs + 16448;      // 4096 [i][o]
    float* w1  = wsk + 4096;      // 2048 [i][j]
    float* w2  = w1 + 2048;       // 2048 [j][o]
    float* Gr  = w2 + 2048;       // 1024 [ky][o][2]
    float* tc  = Gr + 1024;       // 256  cos(2pi t/256)
    float* tsp = tc + 256;        // 256  sin(2pi t/256)
    float* gw  = tsp + 256;       // 64
    float* sb  = gw + 64;         // 64
    float* b1s = sb + 64;         // 32
    float* b2s = b1s + 32;        // 64  -> total 26400 floats = 105600B
    int tid = threadIdx.x;
    int u = blockIdx.x & 255, b = blockIdx.x >> 8;
    float* row = g_h + (size_t)(b*256+u)*64*256;

    for (int i = tid; i < 16384; i += 256) hs[(i>>8)*257 + (i&255)] = row[i];
    for (int i = tid; i < 4096; i += 256){ int ii = i>>6, o = i&63; wsk[i] = wskip_g[l*4096 + o*64 + ii]; }
    for (int i = tid; i < 2048; i += 256){ int ii = i>>5, j = i&31; w1[i]  = w1_g[l*2048 + j*64 + ii]; }
    for (int i = tid; i < 2048; i += 256){ int j = i>>6, o = i&63;  w2[i]  = w2_g[l*2048 + o*32 + j]; }
    for (int i = tid; i < 1024; i += 256){ int ky = i>>7, r = i&127; Gr[i] = g_G[(size_t)(((b*8+ky)*256+u)*64)*2 + r]; }
    {
        float ss, sc;
        sincospif((float)tid*(1.0f/128.0f), &ss, &sc);
        tc[tid] = sc; tsp[tid] = ss;
    }
    if (tid < 64) gw[tid]  = gate_g[l*64+tid];
    if (tid < 64) sb[tid]  = specb_g[l*64+tid];
    if (tid < 32) b1s[tid] = b1_g[l*32+tid];
    if (tid < 64) b2s[tid] = b2_g[l*64+tid];
    __syncthreads();

    int v = tid;

    // ---- phase 1: acc = spec_b + spectral recombination + skip GEMM, gelu
    float acc[64];
    #pragma unroll
    for (int o = 0; o < 64; o++) acc[o] = sb[o];
    #pragma unroll
    for (int ky = 0; ky < 8; ky++){
        int idx = (ky*v) & 255;
        float cw = (ky == 0) ? 1.0f : 2.0f;
        float cs = tc[idx]*cw, sn = tsp[idx]*cw;
        const float4* gp = (const float4*)&Gr[ky*128];
        #pragma unroll
        for (int o2 = 0; o2 < 32; o2++){
            float4 g = gp[o2];
            acc[o2*2]   = fmaf(g.x, cs, fmaf(-g.y, sn, acc[o2*2]));
            acc[o2*2+1] = fmaf(g.z, cs, fmaf(-g.w, sn, acc[o2*2+1]));
        }
    }
    for (int i = 0; i < 64; i++){
        float hv = hs[i*257 + v];
        const float4* wp = (const float4*)&wsk[i*64];
        #pragma unroll
        for (int o4 = 0; o4 < 16; o4++){
            float4 w = wp[o4];
            acc[o4*4+0] = fmaf(hv, w.x, acc[o4*4+0]);
            acc[o4*4+1] = fmaf(hv, w.y, acc[o4*4+1]);
            acc[o4*4+2] = fmaf(hv, w.z, acc[o4*4+2]);
            acc[o4*4+3] = fmaf(hv, w.w, acc[o4*4+3]);
        }
    }
    #pragma unroll
    for (int o = 0; o < 64; o++) acc[o] = gelu_f(acc[o]);

    // ---- phase 2: m = gelu(W1 t + b1)
    float m[32];
    #pragma unroll
    for (int j = 0; j < 32; j++) m[j] = b1s[j];
    #pragma unroll
    for (int i = 0; i < 64; i++){
        float tv = acc[i];
        const float4* wp = (const float4*)&w1[i*32];
        #pragma unroll
        for (int j4 = 0; j4 < 8; j4++){
            float4 w = wp[j4];
            m[j4*4+0] = fmaf(tv, w.x, m[j4*4+0]);
            m[j4*4+1] = fmaf(tv, w.y, m[j4*4+1]);
            m[j4*4+2] = fmaf(tv, w.z, m[j4*4+2]);
            m[j4*4+3] = fmaf(tv, w.w, m[j4*4+3]);
        }
    }
    #pragma unroll
    for (int j = 0; j < 32; j++) m[j] = gelu_f(m[j]);

    // ---- phase 3: out = W2 m + b2 + gate*h_old (+ gelu if l<3)
    float out[64];
    #pragma unroll
    for (int o = 0; o < 64; o++) out[o] = fmaf(gw[o], hs[o*257 + v], b2s[o]);
    #pragma unroll
    for (int j = 0; j < 32; j++){
        float mv = m[j];
        const float4* wp = (const float4*)&w2[j*64];
        #pragma unroll
        for (int o4 = 0; o4 < 16; o4++){
            float4 w = wp[o4];
            out[o4*4+0] = fmaf(mv, w.x, out[o4*4+0]);
            out[o4*4+1] = fmaf(mv, w.y, out[o4*4+1]);
            out[o4*4+2] = fmaf(mv, w.z, out[o4*4+2]);
            out[o4*4+3] = fmaf(mv, w.w, out[o4*4+3]);
        }
    }
    if (l < 3){
        #pragma unroll
        for (int o = 0; o < 64; o++) out[o] = gelu_f(out[o]);
    }

    __syncthreads();   // all reads of old hs done
    #pragma unroll
    for (int o = 0; o < 64; o++) hs[o*257 + v] = out[o];
    __syncthreads();

    // coalesced writeback of new h
    for (int i = tid; i < 16384; i += 256) row[i] = hs[(i>>8)*257 + (i&255)];

    // ---- epilogue: stage-1 DFT for the next layer
    if (do_dft){
        const float scale = 1.0f/65536.0f;
        #pragma unroll
        for (int rep = 0; rep < 2; rep++){
            int idx = tid + rep*256;
            int ky = idx >> 6, c = idx & 63;
            float sr = 0.f, si = 0.f;
            int kyv = 0;
            for (int v2 = 0; v2 < 256; v2++){
                float xv = hs[c*257 + v2];
                int t = kyv & 255;
                kyv += ky;
                sr = fmaf(xv, tc[t],  sr);
                si = fmaf(xv, tsp[t], si);
            }
            float* o = g_Y + (size_t)(((b*8+ky)*256+u)*64 + c)*2;
            o[0] = sr*scale; o[1] = -si*scale;
        }
    }
}

// ---------------- projection: 64 -> 128 -> gelu -> 3, + input residual ------
__global__ __launch_bounds__(256,2) void k_proj(const float* __restrict__ x,
                      const float* __restrict__ b1g, const float* __restrict__ w2g,
                      const float* __restrict__ b2g, float* __restrict__ out){
    extern __shared__ float sm[];
    float* hsp = sm;            // 64*65
    float* t2  = hsp + 64*65;   // 128*65
    float* w1s = t2 + 128*65;   // 64*128 [k][o]
    float* b1s = w1s + 8192;    // 128
    int tid = threadIdx.x;
    int blk = blockIdx.x;
    int q = blk & 3, u = (blk>>2) & 255, b = blk >> 10;
    const float* row = g_h + (size_t)(b*256+u)*64*256 + q*64;
    for (int i = tid; i < 64*64; i += 256){ int c = i>>6, v = i&63; hsp[c*65+v] = row[c*256+v]; }
    for (int i = tid; i < 8192;  i += 256) w1s[i] = g_Wp1[i];
    if (tid < 128) b1s[tid] = b1g[tid];
    __syncthreads();
    {
        int og = tid >> 6, vv = tid & 63;
        int o0 = og*32;
        float a[32];
        #pragma unroll
        for (int j = 0; j < 32; j++) a[j] = b1s[o0+j];
        for (int k = 0; k < 64; k++){
            float hv = hsp[k*65+vv];
            const float4* wp = (const float4*)&w1s[k*128+o0];
            #pragma unroll
            for (int j4 = 0; j4 < 8; j4++){
                float4 w = wp[j4];
                a[j4*4+0] = fmaf(hv, w.x, a[j4*4+0]);
                a[j4*4+1] = fmaf(hv, w.y, a[j4*4+1]);
                a[j4*4+2] = fmaf(hv, w.z, a[j4*4+2]);
                a[j4*4+3] = fmaf(hv, w.w, a[j4*4+3]);
            }
        }
        #pragma unroll
        for (int j = 0; j < 32; j++) t2[(o0+j)*65+vv] = gelu_f(a[j]);
    }
    __syncthreads();
    if (tid < 192){
        int c = tid >> 6, vv = tid & 63;
        float a = b2g[c];
        for (int j = 0; j < 128; j++)
            a = fmaf(t2[j*65+vv], w2g[c*128+j], a);
        size_t gi = (size_t)((b*3+c)*256+u)*256 + q*64 + vv;
        out[gi] = a + x[gi];
    }
}

// ---------------- host launch ------------------------------------------------
extern "C" void kernel_launch(void* const* d_in, const int* in_sizes, int n_in,
                              void* d_out, int out_size){
    (void)in_sizes; (void)n_in; (void)out_size;
    const float* x       = (const float*)d_in[0];
    const float* lift_w1 = (const float*)d_in[1];
    const float* lift_b1 = (const float*)d_in[2];
    const float* lift_w2 = (const float*)d_in[3];
    const float* lift_b2 = (const float*)d_in[4];
    const float* swr1    = (const float*)d_in[5];
    const float* swi1    = (const float*)d_in[6];
    const float* swr2    = (const float*)d_in[7];
    const float* swi2    = (const float*)d_in[8];
    const float* spec_b  = (const float*)d_in[9];
    const float* skw     = (const float*)d_in[10];
    const float* gate    = (const float*)d_in[11];
    const float* mw1     = (const float*)d_in[12];
    const float* mb1     = (const float*)d_in[13];
    const float* mw2     = (const float*)d_in[14];
    const float* mb2     = (const float*)d_in[15];
    const float* pw1     = (const float*)d_in[16];
    const float* pb1     = (const float*)d_in[17];
    const float* pw2     = (const float*)d_in[18];
    const float* pb2     = (const float*)d_in[19];
    float* out = (float*)d_out;

    const int SM_LIFT = (16512 + 8192 + 768 + 256 + 64 + 384) * 4;   // 104704
    const int SM_DFT1 = (64*257 + 8*256*2) * 4;                       // 82176
    const int SM_FUSE = 26400 * 4;                                    // 105600
    const int SM_PROJ = (64*65 + 128*65 + 8192 + 128) * 4;            // 83200

    cudaFuncSetAttribute(k_lift, cudaFuncAttributeMaxDynamicSharedMemorySize, SM_LIFT);
    cudaFuncSetAttribute(k_dft1, cudaFuncAttributeMaxDynamicSharedMemorySize, SM_DFT1);
    cudaFuncSetAttribute(k_fuse, cudaFuncAttributeMaxDynamicSharedMemorySize, SM_FUSE);
    cudaFuncSetAttribute(k_proj, cudaFuncAttributeMaxDynamicSharedMemorySize, SM_PROJ);

    k_reorder<<<64, 256>>>(lift_w2, pw1);
    k_lift<<<BB*HH*2, 256, SM_LIFT>>>(x, lift_w1, lift_b1, lift_b2);
    k_dft1<<<BB*HH, 256, SM_DFT1>>>();           // once, after lift
    for (int l = 0; l < 4; l++){
        k_dft2 <<<BB*NKY*NKX, 256>>>();
        k_mix  <<<NKX*NKY, 256>>>(l, swr1, swi1, swr2, swi2);
        k_idft1<<<BB*NKY*4, 256>>>();
        k_fuse <<<BB*HH, 256, SM_FUSE>>>(l, (l < 3) ? 1 : 0,
                                         skw, gate, spec_b, mw1, mb1, mw2, mb2);
    }
    k_proj<<<BB*HH*4, 256, SM_PROJ>>>(x, pb1, pw2, pb2, out);
}